// round 3
// baseline (speedup 1.0000x reference)
#include <cuda_runtime.h>
#include <math.h>

// ChamferReward — R3: index-free FMNMX inner loop + chunk rescan for argmin.
//
// Inner loop tracks only the chunk-min value (FMNMX, alu pipe) — no FSETP/SEL/
// index updates. Chunk boundaries (every 16 jp) fold into (bestd, bestchunk)
// with strict < (first chunk wins). The winning 16-jp chunk is rescanned with
// the bit-identical FMA2 sequence and exact == to recover the first argmin
// index (lo before hi => jnp.argmin first-tie semantics).
//
// B-side smem packed for LDS.128: sb01[jp] = {b0(j,j+1), b1(j,j+1)},
// sb23[jp] = {b2 pair, b3 pair}, sbb[jp] = |b|^2 pair.

#define N_PART  1024
#define NJP     512
#define THREADS 256
#define ITEMS   4
#define CJP     16      // jp per chunk
#define NCHUNK  (NJP / CJP)

typedef unsigned long long ull;

__device__ float g_partials[1024];

#define FMA2(d, a, b, c) \
    asm("fma.rn.f32x2 %0, %1, %2, %3;" : "=l"(d) : "l"(a), "l"(b), "l"(c))

__device__ __forceinline__ ull pack_dup(float x) {
    ull r;
    unsigned xi = __float_as_uint(x);
    asm("mov.b64 %0, {%1, %1};" : "=l"(r) : "r"(xi));
    return r;
}

__device__ __forceinline__ void unpack2(ull v, float& lo, float& hi) {
    unsigned a, b;
    asm("mov.b64 {%0, %1}, %2;" : "=r"(a), "=r"(b) : "l"(v));
    lo = __uint_as_float(a);
    hi = __uint_as_float(b);
}

__global__ void __launch_bounds__(THREADS)
chamfer_pass_kernel(const float* __restrict__ achieved,
                    const float* __restrict__ desired,
                    const float* __restrict__ norm_mean,
                    const float* __restrict__ norm_std)
{
    __shared__ ulonglong2 sb01[NJP];  // 8KB: {b0 pair, b1 pair}
    __shared__ ulonglong2 sb23[NJP];  // 8KB: {b2 pair, b3 pair}
    __shared__ ull        sbb[NJP];   // 4KB: |b|^2 pair
    __shared__ float2     sxy[N_PART];// 8KB
    __shared__ float      warp_sums[THREADS / 32];

    const int c    = blockIdx.x;
    const int pass = c & 1;
    const int bv   = c >> 1;

    const float* ownp;
    const float* strp;
    if (pass == 0) { ownp = desired;  strp = achieved; }
    else           { ownp = achieved; strp = desired;  }
    const size_t base = (size_t)bv * (size_t)N_PART * 10;
    ownp += base;
    strp += base;

    const float m0 = __ldg(norm_mean + 0), m1 = __ldg(norm_mean + 1);
    const float m5 = __ldg(norm_mean + 5), m6 = __ldg(norm_mean + 6);
    const float m7 = __ldg(norm_mean + 7), m8 = __ldg(norm_mean + 8);
    const float s0 = __ldg(norm_std  + 0), s1 = __ldg(norm_std  + 1);
    const float s5 = __ldg(norm_std  + 5), s6 = __ldg(norm_std  + 6);
    const float s7 = __ldg(norm_std  + 7), s8 = __ldg(norm_std  + 8);

    const int tid = threadIdx.x;

    // ---- Stage streamed side (normalize, precompute |vis|^2) ----
    {
        float* f01 = (float*)sb01;   // layout per jp: [b0_lo, b0_hi, b1_lo, b1_hi]
        float* f23 = (float*)sb23;   // layout per jp: [b2_lo, b2_hi, b3_lo, b3_hi]
        float* fbb = (float*)sbb;    // contiguous over j
        for (int i = tid; i < N_PART; i += THREADS) {
            const float* r = strp + i * 10;
            float x0 = fmaf(r[0], s0, m0);
            float x1 = fmaf(r[1], s1, m1);
            float v0 = fmaf(r[5], s5, m5);
            float v1 = fmaf(r[6], s6, m6);
            float v2 = fmaf(r[7], s7, m7);
            float v3 = fmaf(r[8], s8, m8);
            const int jp = i >> 1, h = i & 1;
            f01[jp * 4 + h]     = v0;
            f01[jp * 4 + 2 + h] = v1;
            f23[jp * 4 + h]     = v2;
            f23[jp * 4 + 2 + h] = v3;
            fbb[i] = v0 * v0 + v1 * v1 + v2 * v2 + v3 * v3;
            sxy[i] = make_float2(x0, x1);
        }
    }

    // ---- Owned items: a' = -2a, duplicated into both packed halves ----
    ull a0d[ITEMS], a1d[ITEMS], a2d[ITEMS], a3d[ITEMS];
    float aa[ITEMS], ox[ITEMS], oy[ITEMS];
#pragma unroll
    for (int k = 0; k < ITEMS; k++) {
        const int i = tid + k * THREADS;
        const float* r = ownp + i * 10;
        ox[k] = fmaf(r[0], s0, m0);
        oy[k] = fmaf(r[1], s1, m1);
        float a0 = fmaf(r[5], s5, m5);
        float a1 = fmaf(r[6], s6, m6);
        float a2 = fmaf(r[7], s7, m7);
        float a3 = fmaf(r[8], s8, m8);
        aa[k] = a0 * a0 + a1 * a1 + a2 * a2 + a3 * a3;
        a0d[k] = pack_dup(-2.0f * a0);
        a1d[k] = pack_dup(-2.0f * a1);
        a2d[k] = pack_dup(-2.0f * a2);
        a3d[k] = pack_dup(-2.0f * a3);
    }

    __syncthreads();

    // ---- Main loop: value-only chunk minima (no index tracking) ----
    float bestd[ITEMS];
    int   bestc[ITEMS];
#pragma unroll
    for (int k = 0; k < ITEMS; k++) { bestd[k] = 3.4e38f; bestc[k] = 0; }

    for (int ch = 0; ch < NCHUNK; ch++) {
        float cb[ITEMS];
#pragma unroll
        for (int k = 0; k < ITEMS; k++) cb[k] = 3.4e38f;

#pragma unroll 8
        for (int u = 0; u < CJP; u++) {
            const int jp = (ch << 4) + u;
            const ulonglong2 p01 = sb01[jp];
            const ulonglong2 p23 = sb23[jp];
            const ull        acc = sbb[jp];
#pragma unroll
            for (int k = 0; k < ITEMS; k++) {
                ull t;
                FMA2(t, a0d[k], p01.x, acc);
                FMA2(t, a1d[k], p01.y, t);
                FMA2(t, a2d[k], p23.x, t);
                FMA2(t, a3d[k], p23.y, t);
                float lo, hi;
                unpack2(t, lo, hi);
                cb[k] = fminf(cb[k], lo);
                cb[k] = fminf(cb[k], hi);
            }
        }
#pragma unroll
        for (int k = 0; k < ITEMS; k++)
            if (cb[k] < bestd[k]) { bestd[k] = cb[k]; bestc[k] = ch; }  // strict <: first chunk wins
    }

    // ---- Rescan winning chunk per item: recover first argmin index exactly ----
    float partial = 0.0f;
#pragma unroll
    for (int k = 0; k < ITEMS; k++) {
        const float bd = bestd[k];
        const int jp0 = bestc[k] << 4;
        int jbest = jp0 * 2;
        bool found = false;
        for (int u = 0; u < CJP; u++) {
            const int jp = jp0 + u;
            const ulonglong2 p01 = sb01[jp];
            const ulonglong2 p23 = sb23[jp];
            const ull        acc = sbb[jp];
            ull t;
            FMA2(t, a0d[k], p01.x, acc);
            FMA2(t, a1d[k], p01.y, t);
            FMA2(t, a2d[k], p23.x, t);
            FMA2(t, a3d[k], p23.y, t);
            float lo, hi;
            unpack2(t, lo, hi);
            if (!found && lo == bd) { jbest = jp * 2;     found = true; }
            if (!found && hi == bd) { jbest = jp * 2 + 1; found = true; }
        }

        const float2 p = sxy[jbest];
        const float dx = ox[k] - p.x;
        const float dy = oy[k] - p.y;
        float xd = sqrtf(dx * dx + dy * dy);
        const float min_d = aa[k] + bd;     // true squared latent distance
        if (min_d > 6.0f) xd = 1.0f;        // LATENT_DIST_THRESHOLD
        partial += xd;
    }

    // ---- Block reduce (deterministic) ----
#pragma unroll
    for (int off = 16; off > 0; off >>= 1)
        partial += __shfl_down_sync(0xffffffffu, partial, off);
    if ((tid & 31) == 0) warp_sums[tid >> 5] = partial;
    __syncthreads();
    if (tid == 0) {
        float s = 0.0f;
#pragma unroll
        for (int w = 0; w < THREADS / 32; w++) s += warp_sums[w];
        g_partials[c] = s;
    }
}

__global__ void chamfer_reduce_kernel(float* __restrict__ out)
{
    const int b = threadIdx.x;   // 128 threads
    float s = 0.0f;
#pragma unroll
    for (int t = 0; t < 8; t++) s += g_partials[b * 8 + t];
    out[b] = -s * (1.0f / (1024.0f * 8.0f));
}

extern "C" void kernel_launch(void* const* d_in, const int* in_sizes, int n_in,
                              void* d_out, int out_size)
{
    const float* achieved  = (const float*)d_in[0];
    const float* desired   = (const float*)d_in[1];
    const float* norm_mean = (const float*)d_in[2];
    const float* norm_std  = (const float*)d_in[3];
    float* out = (float*)d_out;

    chamfer_pass_kernel<<<1024, THREADS>>>(achieved, desired, norm_mean, norm_std);
    chamfer_reduce_kernel<<<1, 128>>>(out);
}

// round 5
// speedup vs baseline: 1.1665x; 1.1665x over previous
#include <cuda_runtime.h>
#include <math.h>

// ChamferReward — R5: chunked index-free argmin; packed FMA2 distance, scalar
// dual-chain fminf min-tracking (lo/hi chains independent), CJP=8 chunks,
// __launch_bounds__(256,2) to pin 2 CTAs/SM and avoid the R3 spill/occupancy
// regression. unpack2 is register-naming only (mov.b64 {r,r} -> 0 SASS).
//
// Winning chunk rescanned with bit-identical FMA order + exact == (lo before
// hi) => jnp.argmin first-occurrence semantics preserved exactly.

#define N_PART  1024
#define NJP     512
#define THREADS 256
#define ITEMS   4
#define CJP     8               // jp per chunk (16 j)
#define NCHUNK  (NJP / CJP)     // 64

typedef unsigned long long ull;

__device__ float g_partials[1024];

#define FMA2(d, a, b, c) \
    asm("fma.rn.f32x2 %0, %1, %2, %3;" : "=l"(d) : "l"(a), "l"(b), "l"(c))

__device__ __forceinline__ ull pack_dup(float x) {
    ull r;
    unsigned xi = __float_as_uint(x);
    asm("mov.b64 %0, {%1, %1};" : "=l"(r) : "r"(xi));
    return r;
}

__device__ __forceinline__ void unpack2(ull v, float& lo, float& hi) {
    unsigned a, b;
    asm("mov.b64 {%0, %1}, %2;" : "=r"(a), "=r"(b) : "l"(v));
    lo = __uint_as_float(a);
    hi = __uint_as_float(b);
}

__global__ void __launch_bounds__(THREADS, 2)
chamfer_pass_kernel(const float* __restrict__ achieved,
                    const float* __restrict__ desired,
                    const float* __restrict__ norm_mean,
                    const float* __restrict__ norm_std)
{
    __shared__ ulonglong2 sb01[NJP];   // 8KB: {b0 pair, b1 pair}
    __shared__ ulonglong2 sb23[NJP];   // 8KB: {b2 pair, b3 pair}
    __shared__ ull        sbb[NJP];    // 4KB: |b|^2 pair
    __shared__ float2     sxy[N_PART]; // 8KB
    __shared__ float      warp_sums[THREADS / 32];

    const int c    = blockIdx.x;
    const int pass = c & 1;
    const int bv   = c >> 1;

    const float* ownp;
    const float* strp;
    if (pass == 0) { ownp = desired;  strp = achieved; }
    else           { ownp = achieved; strp = desired;  }
    const size_t base = (size_t)bv * (size_t)N_PART * 10;
    ownp += base;
    strp += base;

    const float m0 = __ldg(norm_mean + 0), m1 = __ldg(norm_mean + 1);
    const float m5 = __ldg(norm_mean + 5), m6 = __ldg(norm_mean + 6);
    const float m7 = __ldg(norm_mean + 7), m8 = __ldg(norm_mean + 8);
    const float s0 = __ldg(norm_std  + 0), s1 = __ldg(norm_std  + 1);
    const float s5 = __ldg(norm_std  + 5), s6 = __ldg(norm_std  + 6);
    const float s7 = __ldg(norm_std  + 7), s8 = __ldg(norm_std  + 8);

    const int tid = threadIdx.x;

    // ---- Stage streamed side (normalize, precompute |vis|^2) ----
    {
        float* f01 = (float*)sb01;   // per jp: [b0_lo, b0_hi, b1_lo, b1_hi]
        float* f23 = (float*)sb23;   // per jp: [b2_lo, b2_hi, b3_lo, b3_hi]
        float* fbb = (float*)sbb;    // contiguous over j
        for (int i = tid; i < N_PART; i += THREADS) {
            const float* r = strp + i * 10;
            float x0 = fmaf(r[0], s0, m0);
            float x1 = fmaf(r[1], s1, m1);
            float v0 = fmaf(r[5], s5, m5);
            float v1 = fmaf(r[6], s6, m6);
            float v2 = fmaf(r[7], s7, m7);
            float v3 = fmaf(r[8], s8, m8);
            const int jp = i >> 1, h = i & 1;
            f01[jp * 4 + h]     = v0;
            f01[jp * 4 + 2 + h] = v1;
            f23[jp * 4 + h]     = v2;
            f23[jp * 4 + 2 + h] = v3;
            fbb[i] = v0 * v0 + v1 * v1 + v2 * v2 + v3 * v3;
            sxy[i] = make_float2(x0, x1);
        }
    }

    // ---- Owned items: a' = -2a, duplicated into both packed halves ----
    ull a0d[ITEMS], a1d[ITEMS], a2d[ITEMS], a3d[ITEMS];
    float aa[ITEMS], ox[ITEMS], oy[ITEMS];
#pragma unroll
    for (int k = 0; k < ITEMS; k++) {
        const int i = tid + k * THREADS;
        const float* r = ownp + i * 10;
        ox[k] = fmaf(r[0], s0, m0);
        oy[k] = fmaf(r[1], s1, m1);
        float a0 = fmaf(r[5], s5, m5);
        float a1 = fmaf(r[6], s6, m6);
        float a2 = fmaf(r[7], s7, m7);
        float a3 = fmaf(r[8], s8, m8);
        aa[k] = a0 * a0 + a1 * a1 + a2 * a2 + a3 * a3;
        a0d[k] = pack_dup(-2.0f * a0);
        a1d[k] = pack_dup(-2.0f * a1);
        a2d[k] = pack_dup(-2.0f * a2);
        a3d[k] = pack_dup(-2.0f * a3);
    }

    __syncthreads();

    // ---- Main loop: dual-chain value-only chunk minima ----
    float bestd[ITEMS];
    int   bestc[ITEMS];
#pragma unroll
    for (int k = 0; k < ITEMS; k++) { bestd[k] = 3.4e38f; bestc[k] = 0; }

    for (int ch = 0; ch < NCHUNK; ch++) {
        float clo[ITEMS], chi[ITEMS];
#pragma unroll
        for (int k = 0; k < ITEMS; k++) { clo[k] = 3.4e38f; chi[k] = 3.4e38f; }

#pragma unroll
        for (int u = 0; u < CJP; u++) {
            const int jp = ch * CJP + u;
            const ulonglong2 p01 = sb01[jp];
            const ulonglong2 p23 = sb23[jp];
            const ull        acc = sbb[jp];
#pragma unroll
            for (int k = 0; k < ITEMS; k++) {
                ull t;
                FMA2(t, a0d[k], p01.x, acc);
                FMA2(t, a1d[k], p01.y, t);
                FMA2(t, a2d[k], p23.x, t);
                FMA2(t, a3d[k], p23.y, t);
                float lo, hi;
                unpack2(t, lo, hi);       // register-naming only
                clo[k] = fminf(clo[k], lo);
                chi[k] = fminf(chi[k], hi);
            }
        }
#pragma unroll
        for (int k = 0; k < ITEMS; k++) {
            const float m = fminf(clo[k], chi[k]);
            if (m < bestd[k]) { bestd[k] = m; bestc[k] = ch; }  // strict <: first chunk wins
        }
    }

    // ---- Rescan winning chunk per item: recover first argmin index exactly ----
    float partial = 0.0f;
#pragma unroll
    for (int k = 0; k < ITEMS; k++) {
        const float bd = bestd[k];
        const int jp0 = bestc[k] * CJP;
        int jbest = jp0 * 2;
        bool found = false;
        for (int u = 0; u < CJP; u++) {
            const int jp = jp0 + u;
            const ulonglong2 p01 = sb01[jp];
            const ulonglong2 p23 = sb23[jp];
            const ull        acc = sbb[jp];
            ull t;
            FMA2(t, a0d[k], p01.x, acc);
            FMA2(t, a1d[k], p01.y, t);
            FMA2(t, a2d[k], p23.x, t);
            FMA2(t, a3d[k], p23.y, t);
            float lo, hi;
            unpack2(t, lo, hi);
            if (!found && lo == bd) { jbest = jp * 2;     found = true; }
            if (!found && hi == bd) { jbest = jp * 2 + 1; found = true; }
        }

        const float2 p = sxy[jbest];
        const float dx = ox[k] - p.x;
        const float dy = oy[k] - p.y;
        float xd = sqrtf(dx * dx + dy * dy);
        const float min_d = aa[k] + bd;     // true squared latent distance
        if (min_d > 6.0f) xd = 1.0f;        // LATENT_DIST_THRESHOLD
        partial += xd;
    }

    // ---- Block reduce (deterministic) ----
#pragma unroll
    for (int off = 16; off > 0; off >>= 1)
        partial += __shfl_down_sync(0xffffffffu, partial, off);
    if ((tid & 31) == 0) warp_sums[tid >> 5] = partial;
    __syncthreads();
    if (tid == 0) {
        float s = 0.0f;
#pragma unroll
        for (int w = 0; w < THREADS / 32; w++) s += warp_sums[w];
        g_partials[c] = s;
    }
}

__global__ void chamfer_reduce_kernel(float* __restrict__ out)
{
    const int b = threadIdx.x;   // 128 threads
    float s = 0.0f;
#pragma unroll
    for (int t = 0; t < 8; t++) s += g_partials[b * 8 + t];
    out[b] = -s * (1.0f / (1024.0f * 8.0f));
}

extern "C" void kernel_launch(void* const* d_in, const int* in_sizes, int n_in,
                              void* d_out, int out_size)
{
    const float* achieved  = (const float*)d_in[0];
    const float* desired   = (const float*)d_in[1];
    const float* norm_mean = (const float*)d_in[2];
    const float* norm_std  = (const float*)d_in[3];
    float* out = (float*)d_out;

    chamfer_pass_kernel<<<1024, THREADS>>>(achieved, desired, norm_mean, norm_std);
    chamfer_reduce_kernel<<<1, 128>>>(out);
}